// round 14
// baseline (speedup 1.0000x reference)
#include <cuda_runtime.h>
#include <cuda_bf16.h>
#include <math.h>
#include <stdint.h>

// ---------------- scratch (device globals; no allocation) ----------------
__device__ float S_x [128u*512u*196u];   // reduced features (b 0..63 = feature2, 64..127 = feature3)
__device__ float S_e [128u*512u*512u];   // exp(-xxt)
__device__ float S_rs[128u*512u*4u];     // partial row sums of e (4 parts)
__device__ float S_y [128u*512u*196u];   // att @ xf
__device__ float S_zp[128u*512u*3u];     // partial pooled conv sums (<=3 tile-slots per batch)
__device__ float S_fc[128u*200u];        // per-batch fc output

#define BM 128
#define BN 128
#define BK 16
#define APAD 20            // tf32 A smem row pitch (floats)
#define BROW 136           // tf32 B smem row pitch (floats)
#define EPS 1e-5f
#define NB 196             // spatial columns per batch
#define TP 132             // transpose smem pitch (floats)

#define ASZ (BM*APAD)      // 2560 floats
#define BSZ (BK*BROW)      // 2176 floats

// ---- bf16 G1 kernel geometry ----
#define BK2 32             // k per tile (2 x k16 mma steps)
#define APB 80             // A bf16 row pitch in BYTES (40 bf16)
#define BPPU 136           // B packed row pitch in UINTS
#define A_LAYER_B (128*APB)        // 10240 B
#define B_LAYER_B (16*BPPU*4)      // 8704 B
#define STG_B (2*A_LAYER_B + 2*B_LAYER_B)   // 37888 B
#define G1_SMEM (2*STG_B)                    // 75776 B

__device__ __forceinline__ unsigned f2tf32(float v) {
    unsigned r;
    asm("cvt.rna.tf32.f32 %0, %1;" : "=r"(r) : "f"(v));
    return r;
}

__device__ __forceinline__ void mma_tf32(float* c, const unsigned* a, unsigned b0, unsigned b1) {
    asm volatile(
        "mma.sync.aligned.m16n8k8.row.col.f32.tf32.tf32.f32 "
        "{%0,%1,%2,%3}, {%4,%5,%6,%7}, {%8,%9}, {%0,%1,%2,%3};\n"
        : "+f"(c[0]), "+f"(c[1]), "+f"(c[2]), "+f"(c[3])
        : "r"(a[0]), "r"(a[1]), "r"(a[2]), "r"(a[3]), "r"(b0), "r"(b1));
}

__device__ __forceinline__ void mma_bf16(float* c, const unsigned* a, unsigned b0, unsigned b1) {
    asm volatile(
        "mma.sync.aligned.m16n8k16.row.col.f32.bf16.bf16.f32 "
        "{%0,%1,%2,%3}, {%4,%5,%6,%7}, {%8,%9}, {%0,%1,%2,%3};\n"
        : "+f"(c[0]), "+f"(c[1]), "+f"(c[2]), "+f"(c[3])
        : "r"(a[0]), "r"(a[1]), "r"(a[2]), "r"(a[3]), "r"(b0), "r"(b1));
}

__device__ __forceinline__ void ldsm4(unsigned& r0, unsigned& r1, unsigned& r2, unsigned& r3,
                                      const void* p) {
    unsigned addr = (unsigned)__cvta_generic_to_shared(p);
    asm volatile("ldmatrix.sync.aligned.m8n8.x4.shared.b16 {%0,%1,%2,%3}, [%4];"
                 : "=r"(r0), "=r"(r1), "=r"(r2), "=r"(r3) : "r"(addr));
}

__device__ __forceinline__ unsigned pack_bf16(float lo, float hi) {
    unsigned r;
    asm("cvt.rn.bf16x2.f32 %0, %1, %2;" : "=r"(r) : "f"(hi), "f"(lo));
    return r;
}
__device__ __forceinline__ float bf16_round(float v) {
    return __bfloat162float(__float2bfloat16(v));
}

// =================== G1: bf16 triple-product reduce conv ===================
__launch_bounds__(256, 2)
__global__ void g1_bf16(const float* __restrict__ Ag, const float* __restrict__ Bg,
                        float* __restrict__ Cg,
                        const float* __restrict__ bias,
                        const float* __restrict__ gamma, const float* __restrict__ beta,
                        const float* __restrict__ mean, const float* __restrict__ var)
{
    extern __shared__ char smc[];

    const int tid = threadIdx.x;
    const int lane = tid & 31;
    const int warp = tid >> 5;
    const int wm = warp >> 2;
    const int wn = warp & 3;
    const int m_blk = blockIdx.y * BM;
    const int n_blk = blockIdx.x * BN;

    float acc[4][4][4];
#pragma unroll
    for (int i = 0; i < 4; i++)
#pragma unroll
        for (int j = 0; j < 4; j++)
#pragma unroll
            for (int q = 0; q < 4; q++) acc[i][j][q] = 0.f;

    const int ar = tid >> 1;
    const int ak = (tid & 1) * 16;
    const int kp = tid >> 4;
    const int n8 = (tid & 15) * 8;

    float aS[16], b0S[8], b1S[8];

    auto loadT = [&](int kt) {
        const int k0 = kt * BK2;
        const float* ap = Ag + (size_t)(m_blk + ar) * 2048 + k0 + ak;
#pragma unroll
        for (int q = 0; q < 4; q++) {
            float4 t = *(const float4*)(ap + q * 4);
            aS[q*4+0]=t.x; aS[q*4+1]=t.y; aS[q*4+2]=t.z; aS[q*4+3]=t.w;
        }
        const int gk0 = k0 + 2 * kp;
#pragma unroll
        for (int ii = 0; ii < 8; ii++) {
            const int gn = n_blk + n8 + ii;
            const int bb = gn / NB;
            const int hw = gn - bb * NB;
            const float* bp = Bg + (size_t)bb * (2048u*NB) + (size_t)gk0 * NB + hw;
            b0S[ii] = bp[0];
            b1S[ii] = bp[NB];
        }
    };

    auto storeT = [&](int st) {
        char* base = smc + st * STG_B;
        char* A0 = base;
        char* A1 = base + A_LAYER_B;
        unsigned* B0 = (unsigned*)(base + 2*A_LAYER_B);
        unsigned* B1 = (unsigned*)(base + 2*A_LAYER_B + B_LAYER_B);
        unsigned uh[8], ul[8];
#pragma unroll
        for (int p = 0; p < 8; p++) {
            const float v0 = aS[2*p], v1 = aS[2*p+1];
            const float h0 = bf16_round(v0), h1 = bf16_round(v1);
            uh[p] = pack_bf16(h0, h1);
            ul[p] = pack_bf16(v0 - h0, v1 - h1);
        }
        {
            char* pa = A0 + ar * APB + ak * 2;
            *(uint4*)pa       = make_uint4(uh[0], uh[1], uh[2], uh[3]);
            *(uint4*)(pa+16)  = make_uint4(uh[4], uh[5], uh[6], uh[7]);
            char* pl = A1 + ar * APB + ak * 2;
            *(uint4*)pl       = make_uint4(ul[0], ul[1], ul[2], ul[3]);
            *(uint4*)(pl+16)  = make_uint4(ul[4], ul[5], ul[6], ul[7]);
        }
        unsigned bh[8], bl[8];
#pragma unroll
        for (int ii = 0; ii < 8; ii++) {
            const float v0 = b0S[ii], v1 = b1S[ii];
            const float h0 = bf16_round(v0), h1 = bf16_round(v1);
            bh[ii] = pack_bf16(h0, h1);
            bl[ii] = pack_bf16(v0 - h0, v1 - h1);
        }
        {
            unsigned* p0 = B0 + kp * BPPU + n8;
            *(uint4*)p0       = make_uint4(bh[0], bh[1], bh[2], bh[3]);
            *(uint4*)(p0+4)   = make_uint4(bh[4], bh[5], bh[6], bh[7]);
            unsigned* p1 = B1 + kp * BPPU + n8;
            *(uint4*)p1       = make_uint4(bl[0], bl[1], bl[2], bl[3]);
            *(uint4*)(p1+4)   = make_uint4(bl[4], bl[5], bl[6], bl[7]);
        }
    };

    loadT(0);
    storeT(0);
    __syncthreads();

    const int lr16 = lane & 15;
    const int lc16 = (lane >> 4) * 16;

    const int ktiles = 2048 / BK2;
    for (int kt = 0; kt < ktiles; kt++) {
        if (kt + 1 < ktiles) loadT(kt + 1);

        char* base = smc + (kt & 1) * STG_B;
        const char* A0 = base;
        const char* A1 = base + A_LAYER_B;
        const unsigned* B0 = (const unsigned*)(base + 2*A_LAYER_B);
        const unsigned* B1 = (const unsigned*)(base + 2*A_LAYER_B + B_LAYER_B);

#pragma unroll
        for (int kh = 0; kh < 2; kh++) {
            unsigned Ah[4][4], Al[4][4];
#pragma unroll
            for (int i = 0; i < 4; i++) {
                const int r = wm * 64 + i * 16 + lr16;
                ldsm4(Ah[i][0], Ah[i][1], Ah[i][2], Ah[i][3],
                      A0 + r * APB + kh * 32 + lc16);
                ldsm4(Al[i][0], Al[i][1], Al[i][2], Al[i][3],
                      A1 + r * APB + kh * 32 + lc16);
            }
            unsigned Bh0[4], Bh1[4], Bl0[4], Bl1[4];
            const int k2a = kh * 8 + (lane & 3);
            const int k2b = k2a + 4;
#pragma unroll
            for (int j = 0; j < 4; j++) {
                const int n = wn * 32 + j * 8 + (lane >> 2);
                Bh0[j] = B0[k2a * BPPU + n];
                Bh1[j] = B0[k2b * BPPU + n];
                Bl0[j] = B1[k2a * BPPU + n];
                Bl1[j] = B1[k2b * BPPU + n];
            }
#pragma unroll
            for (int i = 0; i < 4; i++)
#pragma unroll
                for (int j = 0; j < 4; j++) {
                    mma_bf16(acc[i][j], Ah[i], Bh0[j], Bh1[j]);
                    mma_bf16(acc[i][j], Ah[i], Bl0[j], Bl1[j]);
                    mma_bf16(acc[i][j], Al[i], Bh0[j], Bh1[j]);
                }
        }

        if (kt + 1 < ktiles) storeT((kt + 1) & 1);
        __syncthreads();
    }

    const int g   = lane >> 2;
    const int tig = lane & 3;
#pragma unroll
    for (int i = 0; i < 4; i++) {
        const int r0 = m_blk + wm * 64 + i * 16 + g;
        const int r1 = r0 + 8;
        const float inv0 = gamma[r0] * rsqrtf(var[r0] + EPS);
        const float sh0  = beta[r0] - mean[r0] * inv0 + bias[r0] * inv0;
        const float inv1 = gamma[r1] * rsqrtf(var[r1] + EPS);
        const float sh1  = beta[r1] - mean[r1] * inv1 + bias[r1] * inv1;
#pragma unroll
        for (int j = 0; j < 4; j++) {
            const int c0 = n_blk + wn * 32 + j * 8 + tig * 2;
#pragma unroll
            for (int e = 0; e < 2; e++) {
                const int gn = c0 + e;
                const int bb = gn / NB;
                const int hw = gn - bb * NB;
                float* cb = Cg + (size_t)bb * (512u*NB);
                cb[(size_t)r0 * NB + hw] = fmaxf(fmaf(acc[i][j][e],   inv0, sh0), 0.f);
                cb[(size_t)r1 * NB + hw] = fmaxf(fmaf(acc[i][j][2+e], inv1, sh1), 0.f);
            }
        }
    }
}

// =================== tf32 core (G2/G3/G4) ===================
// MODE 1: NT gemm (symmetric lower-tri), C = exp(-(A*B^T)), row+col sums, mirror [3-term]
// MODE 2: C = (A*B)/rowsum(aux)  (att @ xf)  [1-term]
// MODE 3: im2col 3x3 conv + BN + ReLU + pooled partials [1-term] BATCHED
template<int MODE, int NTERMS, bool BATCHED>
__launch_bounds__(256, 2)
__global__ void gemm_tc(const float* __restrict__ Ag, const float* __restrict__ Bg,
                        float* __restrict__ Cg,
                        int M, int N, int K, int lda, int ldb, int ldc,
                        long long strideA, long long strideB, long long strideC,
                        const float* __restrict__ bias,
                        const float* __restrict__ gamma, const float* __restrict__ beta,
                        const float* __restrict__ mean, const float* __restrict__ var,
                        float* __restrict__ aux, int auxParts)
{
    extern __shared__ float sm[];
    const int ALN = (NTERMS == 1) ? 1 : 2;
    const int BUFSZ = ALN*ASZ + (NTERMS == 3 ? 2 : 1)*BSZ;

    int bxT = blockIdx.x, byT = blockIdx.y;
    if (MODE == 1) {
        const int i = blockIdx.x;
        bxT = (int)((sqrtf(8.f * i + 1.f) - 1.f) * 0.5f);
        byT = i - bxT * (bxT + 1) / 2;
    }

    const int bz = blockIdx.z;
    const float* A = Ag + (size_t)bz * strideA;
    const float* B = BATCHED ? Bg : (Bg + (size_t)bz * strideB);
    float* C = Cg ? (BATCHED ? Cg : Cg + (size_t)bz * strideC) : nullptr;
    float* aux_b = aux ? (BATCHED ? aux : aux + (size_t)bz * (size_t)M * auxParts) : nullptr;

    const int tid = threadIdx.x;
    const int lane = tid & 31;
    const int warp = tid >> 5;
    const int wm = warp >> 2;
    const int wn = warp & 3;
    const int g   = lane >> 2;
    const int tig = lane & 3;

    const int m_blk = byT * BM;
    const int n_blk = bxT * BN;
    const bool nFull = (n_blk + BN <= N);

    float acc[4][4][4];
#pragma unroll
    for (int i = 0; i < 4; i++)
#pragma unroll
        for (int j = 0; j < 4; j++)
#pragma unroll
            for (int q = 0; q < 4; q++) acc[i][j][q] = 0.f;

    const int ar = tid >> 1;
    const int ak = (tid & 1) * 8;
    const int br = tid >> 4;
    const int bc = (tid & 15) * 8;
    const int tn = tid >> 1;
    const int tk = (tid & 1) * 8;

    float aS[8], bS[8];

    const int ktiles = (K + BK - 1) / BK;

    auto loadTile = [&](int kt) {
        const int k0 = kt * BK;
        {
            const float* ap = A + (size_t)(m_blk + ar) * lda + k0 + ak;
            if (k0 + BK <= K) {
                float4 t0 = *(const float4*)ap;
                float4 t1 = *(const float4*)(ap + 4);
                aS[0]=t0.x; aS[1]=t0.y; aS[2]=t0.z; aS[3]=t0.w;
                aS[4]=t1.x; aS[5]=t1.y; aS[6]=t1.z; aS[7]=t1.w;
            } else {
#pragma unroll
                for (int ii = 0; ii < 8; ii++) {
                    const int gk = k0 + ak + ii;
                    aS[ii] = (gk < K) ? ap[ii] : 0.f;
                }
            }
        }
        if (MODE == 1) {
            const float* bp = B + (size_t)(n_blk + tn) * ldb + k0 + tk;
            if (k0 + BK <= K) {
                float4 t0 = *(const float4*)bp;
                float4 t1 = *(const float4*)(bp + 4);
                bS[0]=t0.x; bS[1]=t0.y; bS[2]=t0.z; bS[3]=t0.w;
                bS[4]=t1.x; bS[5]=t1.y; bS[6]=t1.z; bS[7]=t1.w;
            } else {
#pragma unroll
                for (int ii = 0; ii < 8; ii++) {
                    const int gk = k0 + tk + ii;
                    bS[ii] = (gk < K) ? bp[ii] : 0.f;
                }
            }
        } else if (MODE == 3) {
            const int gk = k0 + br;
            const int ci  = gk / 9;
            const int rem = gk - ci * 9;
            const int dy = rem / 3 - 1;
            const int dx = rem - (rem / 3) * 3 - 1;
#pragma unroll
            for (int ii = 0; ii < 8; ii++) {
                const int gn = n_blk + bc + ii;
                float v = 0.f;
                if (gn < N && gk < K) {
                    const int bb = gn / NB;
                    const int hw = gn - bb * NB;
                    const int h = hw / 14, w = hw - (hw / 14) * 14;
                    const int ih = h + dy, iw = w + dx;
                    if (ih >= 0 && ih < 14 && iw >= 0 && iw < 14)
                        v = B[(size_t)bb * strideB + (size_t)ci * NB + ih * 14 + iw];
                }
                bS[ii] = v;
            }
        } else {
            const int gk = k0 + br;
            const bool kok = gk < K;
            const float* bp = B + (size_t)gk * ldb + n_blk + bc;
            if (kok && nFull) {
                float4 t0 = *(const float4*)bp;
                float4 t1 = *(const float4*)(bp + 4);
                bS[0]=t0.x; bS[1]=t0.y; bS[2]=t0.z; bS[3]=t0.w;
                bS[4]=t1.x; bS[5]=t1.y; bS[6]=t1.z; bS[7]=t1.w;
            } else {
#pragma unroll
                for (int ii = 0; ii < 8; ii++) {
                    const int gn = n_blk + bc + ii;
                    bS[ii] = (kok && gn < N) ? bp[ii] : 0.f;
                }
            }
        }
    };

    auto storeTile = [&](int st) {
        float* As_h = sm + st * BUFSZ;
        float* As_l = As_h + ASZ;
        float* Bs_h = As_h + ALN*ASZ;
        float* Bs_l = Bs_h + BSZ;
        float h[8], l[8];
#pragma unroll
        for (int ii = 0; ii < 8; ii++) {
            h[ii] = __uint_as_float(f2tf32(aS[ii]));
            if (NTERMS > 1) l[ii] = aS[ii] - h[ii];
        }
        *(float4*)&As_h[ar * APAD + ak]     = make_float4(h[0], h[1], h[2], h[3]);
        *(float4*)&As_h[ar * APAD + ak + 4] = make_float4(h[4], h[5], h[6], h[7]);
        if (NTERMS > 1) {
            *(float4*)&As_l[ar * APAD + ak]     = make_float4(l[0], l[1], l[2], l[3]);
            *(float4*)&As_l[ar * APAD + ak + 4] = make_float4(l[4], l[5], l[6], l[7]);
        }
#pragma unroll
        for (int ii = 0; ii < 8; ii++) {
            h[ii] = __uint_as_float(f2tf32(bS[ii]));
            if (NTERMS == 3) l[ii] = bS[ii] - h[ii];
        }
        if (MODE == 1) {
#pragma unroll
            for (int ii = 0; ii < 8; ii++) {
                Bs_h[(tk + ii) * BROW + tn] = h[ii];
                if (NTERMS == 3) Bs_l[(tk + ii) * BROW + tn] = l[ii];
            }
        } else {
            *(float4*)&Bs_h[br * BROW + bc]     = make_float4(h[0], h[1], h[2], h[3]);
            *(float4*)&Bs_h[br * BROW + bc + 4] = make_float4(h[4], h[5], h[6], h[7]);
            if (NTERMS == 3) {
                *(float4*)&Bs_l[br * BROW + bc]     = make_float4(l[0], l[1], l[2], l[3]);
                *(float4*)&Bs_l[br * BROW + bc + 4] = make_float4(l[4], l[5], l[6], l[7]);
            }
        }
    };

    loadTile(0);
    storeTile(0);
    __syncthreads();

    const int lrow = lane & 15;
    const int lcol = (lane >> 4) << 2;

    for (int kt = 0; kt < ktiles; kt++) {
        if (kt + 1 < ktiles) loadTile(kt + 1);

        const float* As_h = sm + (kt & 1) * BUFSZ;
        const float* As_l = As_h + ASZ;
        const float* Bs_h = As_h + ALN*ASZ;
        const float* Bs_l = Bs_h + BSZ;

#pragma unroll
        for (int kh = 0; kh < BK; kh += 8) {
            unsigned Ah[4][4], Al[4][4];
#pragma unroll
            for (int i = 0; i < 4; i++) {
                const int r = wm * 64 + i * 16 + lrow;
                ldsm4(Ah[i][0], Ah[i][1], Ah[i][2], Ah[i][3], &As_h[r * APAD + kh + lcol]);
                if (NTERMS > 1)
                    ldsm4(Al[i][0], Al[i][1], Al[i][2], Al[i][3], &As_l[r * APAD + kh + lcol]);
            }
            unsigned Bh[4][2], Bl[4][2];
#pragma unroll
            for (int j = 0; j < 4; j++) {
                const int nb = wn * 32 + j * 8 + g;
                Bh[j][0] = __float_as_uint(Bs_h[(kh + tig) * BROW + nb]);
                Bh[j][1] = __float_as_uint(Bs_h[(kh + tig + 4) * BROW + nb]);
                if (NTERMS == 3) {
                    Bl[j][0] = __float_as_uint(Bs_l[(kh + tig) * BROW + nb]);
                    Bl[j][1] = __float_as_uint(Bs_l[(kh + tig + 4) * BROW + nb]);
                }
            }
#pragma unroll
            for (int i = 0; i < 4; i++)
#pragma unroll
                for (int j = 0; j < 4; j++) {
                    mma_tf32(acc[i][j], Ah[i], Bh[j][0], Bh[j][1]);
                    if (NTERMS == 3) mma_tf32(acc[i][j], Ah[i], Bl[j][0], Bl[j][1]);
                    if (NTERMS > 1)  mma_tf32(acc[i][j], Al[i], Bh[j][0], Bh[j][1]);
                }
        }

        if (kt + 1 < ktiles) storeTile((kt + 1) & 1);
        __syncthreads();
    }

    // ---------------- epilogues ----------------
    if (MODE == 2) {
#pragma unroll
        for (int i = 0; i < 4; i++) {
            const int r0 = m_blk + wm * 64 + i * 16 + g;
            const int r1 = r0 + 8;
            float s0 = 0.f, s1 = 0.f;
            for (int p = 0; p < 4; p++) {
                s0 += aux_b[(size_t)r0 * 4 + p];
                s1 += aux_b[(size_t)r1 * 4 + p];
            }
            const float inv0 = 1.f / s0;
            const float inv1 = 1.f / s1;
#pragma unroll
            for (int j = 0; j < 4; j++) {
                const int c0 = n_blk + wn * 32 + j * 8 + tig * 2;
                if (c0 < N) {
                    float2 v0, v1;
                    v0.x = acc[i][j][0] * inv0;
                    v0.y = acc[i][j][1] * inv0;
                    v1.x = acc[i][j][2] * inv1;
                    v1.y = acc[i][j][3] * inv1;
                    *(float2*)&C[(size_t)r0 * ldc + c0] = v0;
                    *(float2*)&C[(size_t)r1 * ldc + c0] = v1;
                }
            }
        }
    } else if (MODE == 1) {
#pragma unroll
        for (int i = 0; i < 4; i++)
#pragma unroll
            for (int j = 0; j < 4; j++)
#pragma unroll
                for (int q = 0; q < 4; q++) acc[i][j][q] = expf(-acc[i][j][q]);

        float rs0[4], rs1[4];
#pragma unroll
        for (int i = 0; i < 4; i++) { rs0[i] = 0.f; rs1[i] = 0.f; }
#pragma unroll
        for (int i = 0; i < 4; i++) {
            const int r0 = m_blk + wm * 64 + i * 16 + g;
            const int r1 = r0 + 8;
#pragma unroll
            for (int j = 0; j < 4; j++) {
                const int c0 = n_blk + wn * 32 + j * 8 + tig * 2;
                *(float2*)&C[(size_t)r0 * ldc + c0] = make_float2(acc[i][j][0], acc[i][j][1]);
                *(float2*)&C[(size_t)r1 * ldc + c0] = make_float2(acc[i][j][2], acc[i][j][3]);
                rs0[i] += acc[i][j][0] + acc[i][j][1];
                rs1[i] += acc[i][j][2] + acc[i][j][3];
            }
        }
        float* red = sm;
#pragma unroll
        for (int i = 0; i < 4; i++) {
            const int lr = wm * 64 + i * 16 + g;
            red[lr * 16 + wn * 4 + tig]       = rs0[i];
            red[(lr + 8) * 16 + wn * 4 + tig] = rs1[i];
        }
        __syncthreads();
        if (tid < BM) {
            float s = 0.f;
#pragma unroll
            for (int p = 0; p < 16; p++) s += red[tid * 16 + p];
            aux_b[(size_t)(m_blk + tid) * auxParts + bxT] = s;
        }
        __syncthreads();

        if (bxT != byT) {
#pragma unroll
            for (int j = 0; j < 4; j++)
#pragma unroll
                for (int e = 0; e < 2; e++) {
                    float cs = 0.f;
#pragma unroll
                    for (int i = 0; i < 4; i++)
                        cs += acc[i][j][e] + acc[i][j][2 + e];
                    const int c = wn * 32 + j * 8 + tig * 2 + e;
                    red[c * 16 + wm * 8 + g] = cs;
                }
            __syncthreads();
            if (tid < BN) {
                float s = 0.f;
#pragma unroll
                for (int p = 0; p < 16; p++) s += red[tid * 16 + p];
                aux_b[(size_t)(n_blk + tid) * auxParts + byT] = s;
            }
            __syncthreads();

            float* T2 = sm;
#pragma unroll
            for (int i = 0; i < 4; i++)
#pragma unroll
                for (int j = 0; j < 4; j++)
#pragma unroll
                    for (int q = 0; q < 4; q++) {
                        const int r = wm * 64 + i * 16 + g + ((q >= 2) ? 8 : 0);
                        const int c = wn * 32 + j * 8 + tig * 2 + (q & 1);
                        T2[c * TP + r] = acc[i][j][q];
                    }
            __syncthreads();
#pragma unroll
            for (int p = 0; p < 16; p++) {
                const int nr = p * 8 + (tid >> 5);
                const int m4 = (tid & 31) * 4;
                float4 v = *(const float4*)&T2[nr * TP + m4];
                *(float4*)&C[(size_t)(n_blk + nr) * ldc + m_blk + m4] = v;
            }
        }
    } else { // MODE 3 (batched)
        const int b0 = n_blk / NB;
        const int bound = (b0 + 1) * NB;
        float rsb[2][4][2];
#pragma unroll
        for (int u = 0; u < 2; u++)
#pragma unroll
            for (int i = 0; i < 4; i++) { rsb[u][i][0] = 0.f; rsb[u][i][1] = 0.f; }
#pragma unroll
        for (int i = 0; i < 4; i++) {
            const int r0 = m_blk + wm * 64 + i * 16 + g;
            const int r1 = r0 + 8;
            const float inv0 = gamma[r0] * rsqrtf(var[r0] + EPS);
            const float sh0  = beta[r0] - mean[r0] * inv0 + bias[r0] * inv0;
            const float inv1 = gamma[r1] * rsqrtf(var[r1] + EPS);
            const float sh1  = beta[r1] - mean[r1] * inv1 + bias[r1] * inv1;
#pragma unroll
            for (int j = 0; j < 4; j++) {
                const int c0 = n_blk + wn * 32 + j * 8 + tig * 2;
#pragma unroll
                for (int e = 0; e < 2; e++) {
                    const int gn = c0 + e;
                    if (gn < N) {
                        const int u = (gn < bound) ? 0 : 1;
                        rsb[u][i][0] += fmaxf(fmaf(acc[i][j][e],   inv0, sh0), 0.f);
                        rsb[u][i][1] += fmaxf(fmaf(acc[i][j][2+e], inv1, sh1), 0.f);
                    }
                }
            }
        }
        float* red = sm;
#pragma unroll
        for (int u = 0; u < 2; u++) {
            __syncthreads();
#pragma unroll
            for (int i = 0; i < 4; i++) {
                const int lr = wm * 64 + i * 16 + g;
                red[lr * 16 + wn * 4 + tig]       = rsb[u][i][0];
                red[(lr + 8) * 16 + wn * 4 + tig] = rsb[u][i][1];
            }
            __syncthreads();
            if (tid < BM) {
                float s = 0.f;
#pragma unroll
                for (int p = 0; p < 16; p++) s += red[tid * 16 + p];
                const int bb = b0 + u;
                const bool valid = (u == 0) || (bound < n_blk + BN && bound < N);
                if (valid) {
                    const int slot = blockIdx.x - (bb * NB) / BN;
                    aux_b[((size_t)bb * 512 + m_blk + tid) * 3 + slot] = s;
                }
            }
        }
    }
}

__global__ void zero_kernel(float* p, int n)
{
    const int i = blockIdx.x * blockDim.x + threadIdx.x;
    if (i < n) p[i] = 0.f;
}

// ---------------- FC head: z(pool, 3 parts) -> fc1+relu -> fc2 ----------------
__global__ void fc_kernel(const float* __restrict__ zp,
                          const float* __restrict__ fc1w, const float* __restrict__ fc1b,
                          const float* __restrict__ fc2w, const float* __restrict__ fc2b,
                          float* __restrict__ out)
{
    const int b = blockIdx.x;
    __shared__ float zs[512];
    __shared__ float hs[200];
    const int t = threadIdx.x;
    for (int i = t; i < 512; i += blockDim.x) {
        const size_t base = ((size_t)b * 512 + i) * 3;
        zs[i] = (zp[base] + zp[base + 1] + zp[base + 2]) * (1.f / 196.f);
    }
    __syncthreads();
    for (int j = t; j < 200; j += blockDim.x) {
        float s = fc1b[j];
        const float* w = fc1w + (size_t)j * 512;
        for (int k = 0; k < 512; k++) s = fmaf(zs[k], w[k], s);
        hs[j] = fmaxf(s, 0.f);
    }
    __syncthreads();
    for (int j = t; j < 200; j += blockDim.x) {
        float s = fc2b[j];
        const float* w = fc2w + (size_t)j * 200;
        for (int k = 0; k < 200; k++) s = fmaf(hs[k], w[k], s);
        out[(size_t)b * 200 + j] = s;
    }
}

__global__ void combine_kernel(const float* __restrict__ in, float* __restrict__ out)
{
    const int i = blockIdx.x * blockDim.x + threadIdx.x;
    if (i < 64 * 200) out[i] = in[i] + in[i + 64 * 200];
}

// ---------------- host ----------------
extern "C" void kernel_launch(void* const* d_in, const int* in_sizes, int n_in,
                              void* d_out, int out_size)
{
    const float* feature2     = (const float*)d_in[0];
    const float* feature3     = (const float*)d_in[1];
    const float* reduce_w     = (const float*)d_in[2];
    const float* reduce_b     = (const float*)d_in[3];
    const float* reduce_gamma = (const float*)d_in[4];
    const float* reduce_beta  = (const float*)d_in[5];
    const float* reduce_mean  = (const float*)d_in[6];
    const float* reduce_var   = (const float*)d_in[7];
    const float* conv3_w      = (const float*)d_in[8];
    const float* conv3_b      = (const float*)d_in[9];
    const float* conv3_gamma  = (const float*)d_in[10];
    const float* conv3_beta   = (const float*)d_in[11];
    const float* conv3_mean   = (const float*)d_in[12];
    const float* conv3_var    = (const float*)d_in[13];
    const float* fc1_w        = (const float*)d_in[14];
    const float* fc1_b        = (const float*)d_in[15];
    const float* fc2_w        = (const float*)d_in[16];
    const float* fc2_b        = (const float*)d_in[17];
    float* out = (float*)d_out;

    float *sx, *se, *srs, *sy, *szp, *sfc;
    cudaGetSymbolAddress((void**)&sx,  S_x);
    cudaGetSymbolAddress((void**)&se,  S_e);
    cudaGetSymbolAddress((void**)&srs, S_rs);
    cudaGetSymbolAddress((void**)&sy,  S_y);
    cudaGetSymbolAddress((void**)&szp, S_zp);
    cudaGetSymbolAddress((void**)&sfc, S_fc);

    const int SM3 = 2 * (2*ASZ + 2*BSZ) * 4;
    const int SM1 = 2 * (1*ASZ + 1*BSZ) * 4;
    cudaFuncSetAttribute((const void*)g1_bf16,            cudaFuncAttributeMaxDynamicSharedMemorySize, G1_SMEM);
    cudaFuncSetAttribute((const void*)gemm_tc<1,3,false>, cudaFuncAttributeMaxDynamicSharedMemorySize, SM3);
    cudaFuncSetAttribute((const void*)gemm_tc<2,1,false>, cudaFuncAttributeMaxDynamicSharedMemorySize, SM1);
    cudaFuncSetAttribute((const void*)gemm_tc<3,1,true >, cudaFuncAttributeMaxDynamicSharedMemorySize, SM1);

    const dim3 blk(256);

    // G1: reduce 1x1 conv + BN + ReLU, bf16 triple-product. N = 64*196 exact.
    {
        const dim3 g(98, 4, 1);
        g1_bf16<<<g, blk, G1_SMEM>>>(reduce_w, feature2, sx,
                                     reduce_b, reduce_gamma, reduce_beta,
                                     reduce_mean, reduce_var);
        g1_bf16<<<g, blk, G1_SMEM>>>(reduce_w, feature3, sx + (size_t)64 * 512 * NB,
                                     reduce_b, reduce_gamma, reduce_beta,
                                     reduce_mean, reduce_var);
    }
    // G2: e = exp(-xf xf^T), symmetric lower-tri + mirror. M=N=512, K=196
    {
        const dim3 g(10, 1, 128);
        gemm_tc<1,3,false><<<g, blk, SM3>>>(sx, sx, se,
                               512, 512, 196, 196, 196, 512,
                               512LL * 196, 512LL * 196, 512LL * 512,
                               nullptr, nullptr, nullptr, nullptr, nullptr,
                               srs, 4);
    }
    // G3: y = (e @ xf) / rowsum. M=512, N=196, K=512 (per batch), 1-term tf32
    {
        const dim3 g(2, 4, 128);
        gemm_tc<2,1,false><<<g, blk, SM1>>>(se, sx, sy,
                               512, 196, 512, 512, 196, 196,
                               512LL * 512, 512LL * 196, 512LL * 196,
                               nullptr, nullptr, nullptr, nullptr, nullptr,
                               srs, 4);
    }
    // G4: 3x3 conv (im2col) + BN + ReLU + pooled partials, 1-term tf32, batched-N.
    {
        zero_kernel<<<192, 1024>>>(szp, 128*512*3);
        const dim3 g(196, 4, 1);
        gemm_tc<3,1,true><<<g, blk, SM1>>>(conv3_w, sy, nullptr,
                               512, 128*NB, 4608, 4608, 0, 0,
                               0LL, 512LL * NB, 0LL,
                               conv3_b, conv3_gamma, conv3_beta, conv3_mean, conv3_var,
                               szp, 3);
    }
    fc_kernel<<<128, 256>>>(szp, fc1_w, fc1_b, fc2_w, fc2_b, sfc);
    combine_kernel<<<50, 256>>>(sfc, out);
}

// round 16
// speedup vs baseline: 1.0928x; 1.0928x over previous
#include <cuda_runtime.h>
#include <cuda_bf16.h>
#include <math.h>
#include <stdint.h>

// ---------------- scratch (device globals; no allocation) ----------------
__device__ float S_x [128u*512u*196u];   // reduced features (b 0..63 = feature2, 64..127 = feature3)
__device__ float S_e [128u*512u*512u];   // exp(-xxt)
__device__ float S_rs[128u*512u*4u];     // partial row sums of e (4 parts)
__device__ float S_y [128u*512u*196u];   // att @ xf
__device__ float S_zp[128u*512u*3u];     // partial pooled conv sums (<=3 tile-slots per batch)
__device__ float S_fc[128u*200u];        // per-batch fc output

#define BM 128
#define BN 128
#define BK 16
#define APAD 20            // tf32 A smem row pitch (floats)
#define BROW 136           // tf32 B smem row pitch (floats, 3-term path)
#define BPP 264            // paired-B row pitch in floats (132 float2)
#define EPS 1e-5f
#define NB 196             // spatial columns per batch
#define TP 132             // transpose smem pitch (floats)

#define ASZ (BM*APAD)      // 2560 floats
#define BSZ (BK*BROW)      // 2176 floats (>= 8*BPP = 2112)

// ---- bf16 G1 kernel geometry ----
#define BK2 32             // k per tile (2 x k16 mma steps)
#define APB 80             // A bf16 row pitch in BYTES (40 bf16)
#define BPPU 136           // B packed row pitch in UINTS
#define A_LAYER_B (128*APB)        // 10240 B
#define B_LAYER_B (16*BPPU*4)      // 8704 B
#define STG_B (2*A_LAYER_B + 2*B_LAYER_B)   // 37888 B
#define G1_SMEM (2*STG_B)                    // 75776 B

__device__ __forceinline__ unsigned f2tf32(float v) {
    unsigned r;
    asm("cvt.rna.tf32.f32 %0, %1;" : "=r"(r) : "f"(v));
    return r;
}

__device__ __forceinline__ void mma_tf32(float* c, const unsigned* a, unsigned b0, unsigned b1) {
    asm volatile(
        "mma.sync.aligned.m16n8k8.row.col.f32.tf32.tf32.f32 "
        "{%0,%1,%2,%3}, {%4,%5,%6,%7}, {%8,%9}, {%0,%1,%2,%3};\n"
        : "+f"(c[0]), "+f"(c[1]), "+f"(c[2]), "+f"(c[3])
        : "r"(a[0]), "r"(a[1]), "r"(a[2]), "r"(a[3]), "r"(b0), "r"(b1));
}

__device__ __forceinline__ void mma_bf16(float* c, const unsigned* a, unsigned b0, unsigned b1) {
    asm volatile(
        "mma.sync.aligned.m16n8k16.row.col.f32.bf16.bf16.f32 "
        "{%0,%1,%2,%3}, {%4,%5,%6,%7}, {%8,%9}, {%0,%1,%2,%3};\n"
        : "+f"(c[0]), "+f"(c[1]), "+f"(c[2]), "+f"(c[3])
        : "r"(a[0]), "r"(a[1]), "r"(a[2]), "r"(a[3]), "r"(b0), "r"(b1));
}

__device__ __forceinline__ void ldsm4(unsigned& r0, unsigned& r1, unsigned& r2, unsigned& r3,
                                      const void* p) {
    unsigned addr = (unsigned)__cvta_generic_to_shared(p);
    asm volatile("ldmatrix.sync.aligned.m8n8.x4.shared.b16 {%0,%1,%2,%3}, [%4];"
                 : "=r"(r0), "=r"(r1), "=r"(r2), "=r"(r3) : "r"(addr));
}

__device__ __forceinline__ unsigned pack_bf16(float lo, float hi) {
    unsigned r;
    asm("cvt.rn.bf16x2.f32 %0, %1, %2;" : "=r"(r) : "f"(hi), "f"(lo));
    return r;
}
__device__ __forceinline__ float bf16_round(float v) {
    return __bfloat162float(__float2bfloat16(v));
}

// =================== G1: bf16 triple-product reduce conv ===================
__launch_bounds__(256, 2)
__global__ void g1_bf16(const float* __restrict__ Ag, const float* __restrict__ Bg,
                        float* __restrict__ Cg,
                        const float* __restrict__ bias,
                        const float* __restrict__ gamma, const float* __restrict__ beta,
                        const float* __restrict__ mean, const float* __restrict__ var)
{
    extern __shared__ char smc[];

    const int tid = threadIdx.x;
    const int lane = tid & 31;
    const int warp = tid >> 5;
    const int wm = warp >> 2;
    const int wn = warp & 3;
    const int m_blk = blockIdx.y * BM;
    const int n_blk = blockIdx.x * BN;

    float acc[4][4][4];
#pragma unroll
    for (int i = 0; i < 4; i++)
#pragma unroll
        for (int j = 0; j < 4; j++)
#pragma unroll
            for (int q = 0; q < 4; q++) acc[i][j][q] = 0.f;

    const int ar = tid >> 1;
    const int ak = (tid & 1) * 16;
    const int kp = tid >> 4;
    const int n8 = (tid & 15) * 8;

    float aS[16], b0S[8], b1S[8];

    auto loadT = [&](int kt) {
        const int k0 = kt * BK2;
        const float* ap = Ag + (size_t)(m_blk + ar) * 2048 + k0 + ak;
#pragma unroll
        for (int q = 0; q < 4; q++) {
            float4 t = *(const float4*)(ap + q * 4);
            aS[q*4+0]=t.x; aS[q*4+1]=t.y; aS[q*4+2]=t.z; aS[q*4+3]=t.w;
        }
        const int gk0 = k0 + 2 * kp;
#pragma unroll
        for (int ii = 0; ii < 8; ii++) {
            const int gn = n_blk + n8 + ii;
            const int bb = gn / NB;
            const int hw = gn - bb * NB;
            const float* bp = Bg + (size_t)bb * (2048u*NB) + (size_t)gk0 * NB + hw;
            b0S[ii] = bp[0];
            b1S[ii] = bp[NB];
        }
    };

    auto storeT = [&](int st) {
        char* base = smc + st * STG_B;
        char* A0 = base;
        char* A1 = base + A_LAYER_B;
        unsigned* B0 = (unsigned*)(base + 2*A_LAYER_B);
        unsigned* B1 = (unsigned*)(base + 2*A_LAYER_B + B_LAYER_B);
        unsigned uh[8], ul[8];
#pragma unroll
        for (int p = 0; p < 8; p++) {
            const float v0 = aS[2*p], v1 = aS[2*p+1];
            const float h0 = bf16_round(v0), h1 = bf16_round(v1);
            uh[p] = pack_bf16(h0, h1);
            ul[p] = pack_bf16(v0 - h0, v1 - h1);
        }
        {
            char* pa = A0 + ar * APB + ak * 2;
            *(uint4*)pa       = make_uint4(uh[0], uh[1], uh[2], uh[3]);
            *(uint4*)(pa+16)  = make_uint4(uh[4], uh[5], uh[6], uh[7]);
            char* pl = A1 + ar * APB + ak * 2;
            *(uint4*)pl       = make_uint4(ul[0], ul[1], ul[2], ul[3]);
            *(uint4*)(pl+16)  = make_uint4(ul[4], ul[5], ul[6], ul[7]);
        }
        unsigned bh[8], bl[8];
#pragma unroll
        for (int ii = 0; ii < 8; ii++) {
            const float v0 = b0S[ii], v1 = b1S[ii];
            const float h0 = bf16_round(v0), h1 = bf16_round(v1);
            bh[ii] = pack_bf16(h0, h1);
            bl[ii] = pack_bf16(v0 - h0, v1 - h1);
        }
        {
            unsigned* p0 = B0 + kp * BPPU + n8;
            *(uint4*)p0       = make_uint4(bh[0], bh[1], bh[2], bh[3]);
            *(uint4*)(p0+4)   = make_uint4(bh[4], bh[5], bh[6], bh[7]);
            unsigned* p1 = B1 + kp * BPPU + n8;
            *(uint4*)p1       = make_uint4(bl[0], bl[1], bl[2], bl[3]);
            *(uint4*)(p1+4)   = make_uint4(bl[4], bl[5], bl[6], bl[7]);
        }
    };

    loadT(0);
    storeT(0);
    __syncthreads();

    const int lr16 = lane & 15;
    const int lc16 = (lane >> 4) * 16;

    const int ktiles = 2048 / BK2;
    for (int kt = 0; kt < ktiles; kt++) {
        if (kt + 1 < ktiles) loadT(kt + 1);

        char* base = smc + (kt & 1) * STG_B;
        const char* A0 = base;
        const char* A1 = base + A_LAYER_B;
        const unsigned* B0 = (const unsigned*)(base + 2*A_LAYER_B);
        const unsigned* B1 = (const unsigned*)(base + 2*A_LAYER_B + B_LAYER_B);

#pragma unroll
        for (int kh = 0; kh < 2; kh++) {
            unsigned Ah[4][4], Al[4][4];
#pragma unroll
            for (int i = 0; i < 4; i++) {
                const int r = wm * 64 + i * 16 + lr16;
                ldsm4(Ah[i][0], Ah[i][1], Ah[i][2], Ah[i][3],
                      A0 + r * APB + kh * 32 + lc16);
                ldsm4(Al[i][0], Al[i][1], Al[i][2], Al[i][3],
                      A1 + r * APB + kh * 32 + lc16);
            }
            unsigned Bh0[4], Bh1[4], Bl0[4], Bl1[4];
            const int k2a = kh * 8 + (lane & 3);
            const int k2b = k2a + 4;
#pragma unroll
            for (int j = 0; j < 4; j++) {
                const int n = wn * 32 + j * 8 + (lane >> 2);
                Bh0[j] = B0[k2a * BPPU + n];
                Bh1[j] = B0[k2b * BPPU + n];
                Bl0[j] = B1[k2a * BPPU + n];
                Bl1[j] = B1[k2b * BPPU + n];
            }
#pragma unroll
            for (int i = 0; i < 4; i++)
#pragma unroll
                for (int j = 0; j < 4; j++) {
                    mma_bf16(acc[i][j], Ah[i], Bh0[j], Bh1[j]);
                    mma_bf16(acc[i][j], Ah[i], Bl0[j], Bl1[j]);
                    mma_bf16(acc[i][j], Al[i], Bh0[j], Bh1[j]);
                }
        }

        if (kt + 1 < ktiles) storeT((kt + 1) & 1);
        __syncthreads();
    }

    const int g   = lane >> 2;
    const int tig = lane & 3;
#pragma unroll
    for (int i = 0; i < 4; i++) {
        const int r0 = m_blk + wm * 64 + i * 16 + g;
        const int r1 = r0 + 8;
        const float inv0 = gamma[r0] * rsqrtf(var[r0] + EPS);
        const float sh0  = beta[r0] - mean[r0] * inv0 + bias[r0] * inv0;
        const float inv1 = gamma[r1] * rsqrtf(var[r1] + EPS);
        const float sh1  = beta[r1] - mean[r1] * inv1 + bias[r1] * inv1;
#pragma unroll
        for (int j = 0; j < 4; j++) {
            const int c0 = n_blk + wn * 32 + j * 8 + tig * 2;
#pragma unroll
            for (int e = 0; e < 2; e++) {
                const int gn = c0 + e;
                const int bb = gn / NB;
                const int hw = gn - bb * NB;
                float* cb = Cg + (size_t)bb * (512u*NB);
                cb[(size_t)r0 * NB + hw] = fmaxf(fmaf(acc[i][j][e],   inv0, sh0), 0.f);
                cb[(size_t)r1 * NB + hw] = fmaxf(fmaf(acc[i][j][2+e], inv1, sh1), 0.f);
            }
        }
    }
}

// =================== tf32 core (G2/G3/G4) ===================
// MODE 1: NT gemm (symmetric lower-tri), C = exp(-(A*B^T)), row+col sums, mirror [3-term]
// MODE 2: C = (A*B)/rowsum(aux)  (att @ xf)  [1-term, paired-B]
// MODE 3: im2col 3x3 conv + BN + ReLU + pooled partials [1-term, paired-B] BATCHED
template<int MODE, int NTERMS, bool BATCHED>
__launch_bounds__(256, 2)
__global__ void gemm_tc(const float* __restrict__ Ag, const float* __restrict__ Bg,
                        float* __restrict__ Cg,
                        int M, int N, int K, int lda, int ldb, int ldc,
                        long long strideA, long long strideB, long long strideC,
                        const float* __restrict__ bias,
                        const float* __restrict__ gamma, const float* __restrict__ beta,
                        const float* __restrict__ mean, const float* __restrict__ var,
                        float* __restrict__ aux, int auxParts)
{
    extern __shared__ float sm[];
    const int ALN = (NTERMS == 1) ? 1 : 2;
    const int BUFSZ = ALN*ASZ + (NTERMS == 3 ? 2 : 1)*BSZ;

    int bxT = blockIdx.x, byT = blockIdx.y;
    if (MODE == 1) {
        const int i = blockIdx.x;
        bxT = (int)((sqrtf(8.f * i + 1.f) - 1.f) * 0.5f);
        byT = i - bxT * (bxT + 1) / 2;
    }

    const int bz = blockIdx.z;
    const float* A = Ag + (size_t)bz * strideA;
    const float* B = BATCHED ? Bg : (Bg + (size_t)bz * strideB);
    float* C = Cg ? (BATCHED ? Cg : Cg + (size_t)bz * strideC) : nullptr;
    float* aux_b = aux ? (BATCHED ? aux : aux + (size_t)bz * (size_t)M * auxParts) : nullptr;

    const int tid = threadIdx.x;
    const int lane = tid & 31;
    const int warp = tid >> 5;
    const int wm = warp >> 2;
    const int wn = warp & 3;
    const int g   = lane >> 2;
    const int tig = lane & 3;

    const int m_blk = byT * BM;
    const int n_blk = bxT * BN;
    const bool nFull = (n_blk + BN <= N);

    float acc[4][4][4];
#pragma unroll
    for (int i = 0; i < 4; i++)
#pragma unroll
        for (int j = 0; j < 4; j++)
#pragma unroll
            for (int q = 0; q < 4; q++) acc[i][j][q] = 0.f;

    // A staging (all modes) + 3-term B staging indices
    const int ar = tid >> 1;
    const int ak = (tid & 1) * 8;
    const int tn = tid >> 1;               // MODE 1 B n
    const int tk = (tid & 1) * 8;          // MODE 1 B k offset
    // 1-term paired-B staging indices: 2 k-rows (ka, ka+4) x 4 n per thread
    const int pr = tid >> 5;               // pair-row 0..7
    const int n4 = (tid & 31) * 4;         // 0..124
    const int ka = (pr >> 2) * 8 + (pr & 3);

    float aS[8], bS[8];   // 1-term: bS[0..3]=row ka, bS[4..7]=row ka+4

    const int ktiles = (K + BK - 1) / BK;

    auto loadTile = [&](int kt) {
        const int k0 = kt * BK;
        // A
        {
            const float* ap = A + (size_t)(m_blk + ar) * lda + k0 + ak;
            if (k0 + BK <= K) {
                float4 t0 = *(const float4*)ap;
                float4 t1 = *(const float4*)(ap + 4);
                aS[0]=t0.x; aS[1]=t0.y; aS[2]=t0.z; aS[3]=t0.w;
                aS[4]=t1.x; aS[5]=t1.y; aS[6]=t1.z; aS[7]=t1.w;
            } else {
#pragma unroll
                for (int ii = 0; ii < 8; ii++) {
                    const int gk = k0 + ak + ii;
                    aS[ii] = (gk < K) ? ap[ii] : 0.f;
                }
            }
        }
        // B
        if (MODE == 1) {
            const float* bp = B + (size_t)(n_blk + tn) * ldb + k0 + tk;
            if (k0 + BK <= K) {
                float4 t0 = *(const float4*)bp;
                float4 t1 = *(const float4*)(bp + 4);
                bS[0]=t0.x; bS[1]=t0.y; bS[2]=t0.z; bS[3]=t0.w;
                bS[4]=t1.x; bS[5]=t1.y; bS[6]=t1.z; bS[7]=t1.w;
            } else {
#pragma unroll
                for (int ii = 0; ii < 8; ii++) {
                    const int gk = k0 + tk + ii;
                    bS[ii] = (gk < K) ? bp[ii] : 0.f;
                }
            }
        } else if (MODE == 3) {
            // N = 128*196, K = 4608 exact: no gn/gk bounds. Shared n-decode for both k-rows.
            const int gka = k0 + ka;
            const int gkb = gka + 4;
            const int cia  = gka / 9;
            const int rema = gka - cia * 9;
            const int dya = rema / 3 - 1, dxa = rema - (rema / 3) * 3 - 1;
            const int cib  = gkb / 9;
            const int remb = gkb - cib * 9;
            const int dyb = remb / 3 - 1, dxb = remb - (remb / 3) * 3 - 1;
#pragma unroll
            for (int ii = 0; ii < 4; ii++) {
                const int gn = n_blk + n4 + ii;
                const int bb = gn / NB;
                const int hw = gn - bb * NB;
                const int h = hw / 14, w = hw - (hw / 14) * 14;
                const float* yb = B + (size_t)bb * strideB;
                {
                    const int ih = h + dya, iw = w + dxa;
                    bS[ii] = (ih >= 0 && ih < 14 && iw >= 0 && iw < 14)
                               ? yb[(size_t)cia * NB + ih * 14 + iw] : 0.f;
                }
                {
                    const int ih = h + dyb, iw = w + dxb;
                    bS[4+ii] = (ih >= 0 && ih < 14 && iw >= 0 && iw < 14)
                               ? yb[(size_t)cib * NB + ih * 14 + iw] : 0.f;
                }
            }
        } else { // MODE 2: per-batch B [K][N], K multiple of BK
            const int gka = k0 + ka;
            const float* bpa = B + (size_t)gka * ldb + n_blk + n4;
            const float* bpb = bpa + (size_t)4 * ldb;
            if (nFull) {
                float4 ta = *(const float4*)bpa;
                float4 tb = *(const float4*)bpb;
                bS[0]=ta.x; bS[1]=ta.y; bS[2]=ta.z; bS[3]=ta.w;
                bS[4]=tb.x; bS[5]=tb.y; bS[6]=tb.z; bS[7]=tb.w;
            } else {
#pragma unroll
                for (int ii = 0; ii < 4; ii++) {
                    const bool ok = (n_blk + n4 + ii) < N;
                    bS[ii]   = ok ? bpa[ii] : 0.f;
                    bS[4+ii] = ok ? bpb[ii] : 0.f;
                }
            }
        }
    };

    auto storeTile = [&](int st) {
        float* As_h = sm + st * BUFSZ;
        float* As_l = As_h + ASZ;
        float* Bs_h = As_h + ALN*ASZ;
        float* Bs_l = Bs_h + BSZ;
        float h[8], l[8];
#pragma unroll
        for (int ii = 0; ii < 8; ii++) {
            h[ii] = __uint_as_float(f2tf32(aS[ii]));
            if (NTERMS > 1) l[ii] = aS[ii] - h[ii];
        }
        *(float4*)&As_h[ar * APAD + ak]     = make_float4(h[0], h[1], h[2], h[3]);
        *(float4*)&As_h[ar * APAD + ak + 4] = make_float4(h[4], h[5], h[6], h[7]);
        if (NTERMS > 1) {
            *(float4*)&As_l[ar * APAD + ak]     = make_float4(l[0], l[1], l[2], l[3]);
            *(float4*)&As_l[ar * APAD + ak + 4] = make_float4(l[4], l[5], l[6], l[7]);
        }
#pragma unroll
        for (int ii = 0; ii < 8; ii++) {
            h[ii] = __uint_as_float(f2tf32(bS[ii]));
            if (NTERMS == 3) l[ii] = bS[ii] - h[ii];
        }
        if (MODE == 1) {
#pragma unroll
            for (int ii = 0; ii < 8; ii++) {
                Bs_h[(tk + ii) * BROW + tn] = h[ii];
                if (NTERMS == 3) Bs_l[(tk + ii) * BROW + tn] = l[ii];
            }
        } else if (NTERMS == 1) {
            // paired store: {a0,b0,a1,b1} {a2,b2,a3,b3} at row pr, pitch BPP floats
            *(float4*)&Bs_h[pr * BPP + n4 * 2]     = make_float4(h[0], h[4], h[1], h[5]);
            *(float4*)&Bs_h[pr * BPP + n4 * 2 + 4] = make_float4(h[2], h[6], h[3], h[7]);
        }
    };

    loadTile(0);
    storeTile(0);
    __syncthreads();

    const int lrow = lane & 15;
    const int lcol = (lane >> 4) << 2;

    for (int kt = 0; kt < ktiles; kt++) {
        if (kt + 1 < ktiles) loadTile(kt + 1);

        const float* As_h = sm + (kt & 1) * BUFSZ;
        const float* As_l = As_h + ASZ;
        const float* Bs_h = As_h + ALN*ASZ;
        const float* Bs_l = Bs_h + BSZ;

#pragma unroll
        for (int kh = 0; kh < BK; kh += 8) {
            unsigned Ah[4][4], Al[4][4];
#pragma unroll
            for (int i = 0; i < 4; i++) {
                const int r = wm * 64 + i * 16 + lrow;
                ldsm4(Ah[i][0], Ah[i][1], Ah[i][2], Ah[i][3], &As_h[r * APAD + kh + lcol]);
                if (NTERMS > 1)
                    ldsm4(Al[i][0], Al[i][1], Al[i][2], Al[i][3], &As_l[r * APAD + kh + lcol]);
            }
            unsigned Bh[4][2], Bl[4][2];
            if (NTERMS == 1) {
                const int row = ((kh >> 3) * 4 + tig) * BPP;
#pragma unroll
                for (int j = 0; j < 4; j++) {
                    const int nb = wn * 32 + j * 8 + g;
                    float2 bp = *(const float2*)&Bs_h[row + nb * 2];
                    Bh[j][0] = __float_as_uint(bp.x);
                    Bh[j][1] = __float_as_uint(bp.y);
                }
            } else {
#pragma unroll
                for (int j = 0; j < 4; j++) {
                    const int nb = wn * 32 + j * 8 + g;
                    Bh[j][0] = __float_as_uint(Bs_h[(kh + tig) * BROW + nb]);
                    Bh[j][1] = __float_as_uint(Bs_h[(kh + tig + 4) * BROW + nb]);
                    if (NTERMS == 3) {
                        Bl[j][0] = __float_as_uint(Bs_l[(kh + tig) * BROW + nb]);
                        Bl[j][1] = __float_as_uint(Bs_l[(kh + tig + 4) * BROW + nb]);
                    }
                }
            }
#pragma unroll
            for (int i = 0; i < 4; i++)
#pragma unroll
                for (int j = 0; j < 4; j++) {
                    mma_tf32(acc[i][j], Ah[i], Bh[j][0], Bh[j][1]);
                    if (NTERMS == 3) mma_tf32(acc[i][j], Ah[i], Bl[j][0], Bl[j][1]);
                    if (NTERMS > 1)  mma_tf32(acc[i][j], Al[i], Bh[j][0], Bh[j][1]);
                }
        }

        if (kt + 1 < ktiles) storeTile((kt + 1) & 1);
        __syncthreads();
    }

    // ---------------- epilogues ----------------
    if (MODE == 2) {
#pragma unroll
        for (int i = 0; i < 4; i++) {
            const int r0 = m_blk + wm * 64 + i * 16 + g;
            const int r1 = r0 + 8;
            float s0 = 0.f, s1 = 0.f;
            for (int p = 0; p < 4; p++) {
                s0 += aux_b[(size_t)r0 * 4 + p];
                s1 += aux_b[(size_t)r1 * 4 + p];
            }
            const float inv0 = 1.f / s0;
            const float inv1 = 1.f / s1;
#pragma unroll
            for (int j = 0; j < 4; j++) {
                const int c0 = n_blk + wn * 32 + j * 8 + tig * 2;
                if (c0 < N) {
                    float2 v0, v1;
                    v0.x = acc[i][j][0] * inv0;
                    v0.y = acc[i][j][1] * inv0;
                    v1.x = acc[i][j][2] * inv1;
                    v1.y = acc[i][j][3] * inv1;
                    *(float2*)&C[(size_t)r0 * ldc + c0] = v0;
                    *(float2*)&C[(size_t)r1 * ldc + c0] = v1;
                }
            }
        }
    } else if (MODE == 1) {
#pragma unroll
        for (int i = 0; i < 4; i++)
#pragma unroll
            for (int j = 0; j < 4; j++)
#pragma unroll
                for (int q = 0; q < 4; q++) acc[i][j][q] = expf(-acc[i][j][q]);

        float rs0[4], rs1[4];
#pragma unroll
        for (int i = 0; i < 4; i++) { rs0[i] = 0.f; rs1[i] = 0.f; }
#pragma unroll
        for (int i = 0; i < 4; i++) {
            const int r0 = m_blk + wm * 64 + i * 16 + g;
            const int r1 = r0 + 8;
#pragma unroll
            for (int j = 0; j < 4; j++) {
                const int c0 = n_blk + wn * 32 + j * 8 + tig * 2;
                *(float2*)&C[(size_t)r0 * ldc + c0] = make_float2(acc[i][j][0], acc[i][j][1]);
                *(float2*)&C[(size_t)r1 * ldc + c0] = make_float2(acc[i][j][2], acc[i][j][3]);
                rs0[i] += acc[i][j][0] + acc[i][j][1];
                rs1[i] += acc[i][j][2] + acc[i][j][3];
            }
        }
        float* red = sm;
#pragma unroll
        for (int i = 0; i < 4; i++) {
            const int lr = wm * 64 + i * 16 + g;
            red[lr * 16 + wn * 4 + tig]       = rs0[i];
            red[(lr + 8) * 16 + wn * 4 + tig] = rs1[i];
        }
        __syncthreads();
        if (tid < BM) {
            float s = 0.f;
#pragma unroll
            for (int p = 0; p < 16; p++) s += red[tid * 16 + p];
            aux_b[(size_t)(m_blk + tid) * auxParts + bxT] = s;
        }
        __syncthreads();

        if (bxT != byT) {
#pragma unroll
            for (int j = 0; j < 4; j++)
#pragma unroll
                for (int e = 0; e < 2; e++) {
                    float cs = 0.f;
#pragma unroll
                    for (int i = 0; i < 4; i++)
                        cs += acc[i][j][e] + acc[i][j][2 + e];
                    const int c = wn * 32 + j * 8 + tig * 2 + e;
                    red[c * 16 + wm * 8 + g] = cs;
                }
            __syncthreads();
            if (tid < BN) {
                float s = 0.f;
#pragma unroll
                for (int p = 0; p < 16; p++) s += red[tid * 16 + p];
                aux_b[(size_t)(n_blk + tid) * auxParts + byT] = s;
            }
            __syncthreads();

            float* T2 = sm;
#pragma unroll
            for (int i = 0; i < 4; i++)
#pragma unroll
                for (int j = 0; j < 4; j++)
#pragma unroll
                    for (int q = 0; q < 4; q++) {
                        const int r = wm * 64 + i * 16 + g + ((q >= 2) ? 8 : 0);
                        const int c = wn * 32 + j * 8 + tig * 2 + (q & 1);
                        T2[c * TP + r] = acc[i][j][q];
                    }
            __syncthreads();
#pragma unroll
            for (int p = 0; p < 16; p++) {
                const int nr = p * 8 + (tid >> 5);
                const int m4 = (tid & 31) * 4;
                float4 v = *(const float4*)&T2[nr * TP + m4];
                *(float4*)&C[(size_t)(n_blk + nr) * ldc + m_blk + m4] = v;
            }
        }
    } else { // MODE 3 (batched)
        const int b0 = n_blk / NB;
        const int bound = (b0 + 1) * NB;
        float rsb[2][4][2];
#pragma unroll
        for (int u = 0; u < 2; u++)
#pragma unroll
            for (int i = 0; i < 4; i++) { rsb[u][i][0] = 0.f; rsb[u][i][1] = 0.f; }
#pragma unroll
        for (int i = 0; i < 4; i++) {
            const int r0 = m_blk + wm * 64 + i * 16 + g;
            const int r1 = r0 + 8;
            const float inv0 = gamma[r0] * rsqrtf(var[r0] + EPS);
            const float sh0  = beta[r0] - mean[r0] * inv0 + bias[r0] * inv0;
            const float inv1 = gamma[r1] * rsqrtf(var[r1] + EPS);
            const float sh1  = beta[r1] - mean[r1] * inv1 + bias[r1] * inv1;
#pragma unroll
            for (int j = 0; j < 4; j++) {
                const int c0 = n_blk + wn * 32 + j * 8 + tig * 2;
#pragma unroll
                for (int e = 0; e < 2; e++) {
                    const int gn = c0 + e;
                    const int u = (gn < bound) ? 0 : 1;
                    rsb[u][i][0] += fmaxf(fmaf(acc[i][j][e],   inv0, sh0), 0.f);
                    rsb[u][i][1] += fmaxf(fmaf(acc[i][j][2+e], inv1, sh1), 0.f);
                }
            }
        }
        float* red = sm;
#pragma unroll
        for (int u = 0; u < 2; u++) {
            __syncthreads();
#pragma unroll
            for (int i = 0; i < 4; i++) {
                const int lr = wm * 64 + i * 16 + g;
                red[lr * 16 + wn * 4 + tig]       = rsb[u][i][0];
                red[(lr + 8) * 16 + wn * 4 + tig] = rsb[u][i][1];
            }
            __syncthreads();
            if (tid < BM) {
                float s = 0.f;
#pragma unroll
                for (int p = 0; p < 16; p++) s += red[tid * 16 + p];
                const int bb = b0 + u;
                const bool valid = (u == 0) || (bound < n_blk + BN && bound < N);
                if (valid) {
                    const int slot = blockIdx.x - (bb * NB) / BN;
                    aux_b[((size_t)bb * 512 + m_blk + tid) * 3 + slot] = s;
                }
            }
        }
    }
}

__global__ void zero_kernel(float* p, int n)
{
    const int i = blockIdx.x * blockDim.x + threadIdx.x;
    if (i < n) p[i] = 0.f;
}

// ---------------- FC head: z(pool, 3 parts) -> fc1+relu -> fc2 ----------------
__global__ void fc_kernel(const float* __restrict__ zp,
                          const float* __restrict__ fc1w, const float* __restrict__ fc1b,
                          const float* __restrict__ fc2w, const float* __restrict__ fc2b,
                          float* __restrict__ out)
{
    const int b = blockIdx.x;
    __shared__ float zs[512];
    __shared__ float hs[200];
    const int t = threadIdx.x;
    for (int i = t; i < 512; i += blockDim.x) {
        const size_t base = ((size_t)b * 512 + i) * 3;
        zs[i] = (zp[base] + zp[base + 1] + zp[base + 2]) * (1.f / 196.f);
    }
    __syncthreads();
    for (int j = t; j < 200; j += blockDim.x) {
        float s = fc1b[j];
        const float* w = fc1w + (size_t)j * 512;
        for (int k = 0; k < 512; k++) s = fmaf(zs[k], w[k], s);
        hs[j] = fmaxf(s, 0.f);
    }
    __syncthreads();
    for (int j = t; j < 200; j += blockDim.x) {
        float s = fc2b[j];
        const float* w = fc2w + (size_t)j * 200;
        for (int k = 0; k < 200; k++) s = fmaf(hs[k], w[k], s);
        out[(size_t)b * 200 + j] = s;
    }
}

__global__ void combine_kernel(const float* __restrict__ in, float* __restrict__ out)
{
    const int i = blockIdx.x * blockDim.x + threadIdx.x;
    if (i < 64 * 200) out[i] = in[i] + in[i + 64 * 200];
}

// ---------------- host ----------------
extern "C" void kernel_launch(void* const* d_in, const int* in_sizes, int n_in,
                              void* d_out, int out_size)
{
    const float* feature2     = (const float*)d_in[0];
    const float* feature3     = (const float*)d_in[1];
    const float* reduce_w     = (const float*)d_in[2];
    const float* reduce_b     = (const float*)d_in[3];
    const float* reduce_gamma = (const float*)d_in[4];
    const float* reduce_beta  = (const float*)d_in[5];
    const float* reduce_mean  = (const float*)d_in[6];
    const float* reduce_var   = (const float*)d_in[7];
    const float* conv3_w      = (const float*)d_in[8];
    const float* conv3_b      = (const float*)d_in[9];
    const float* conv3_gamma  = (const float*)d_in[10];
    const float* conv3_beta   = (const float*)d_in[11];
    const float* conv3_mean   = (const float*)d_in[12];
    const float* conv3_var    = (const float*)d_in[13];
    const float* fc1_w        = (const float*)d_in[14];
    const float* fc1_b        = (const float*)d_in[15];
    const float* fc2_w        = (const float*)d_in[16];
    const float* fc2_b        = (const float*)d_in[17];
    float* out = (float*)d_out;

    float *sx, *se, *srs, *sy, *szp, *sfc;
    cudaGetSymbolAddress((void**)&sx,  S_x);
    cudaGetSymbolAddress((void**)&se,  S_e);
    cudaGetSymbolAddress((void**)&srs, S_rs);
    cudaGetSymbolAddress((void**)&sy,  S_y);
    cudaGetSymbolAddress((void**)&szp, S_zp);
    cudaGetSymbolAddress((void**)&sfc, S_fc);

    const int SM3 = 2 * (2*ASZ + 2*BSZ) * 4;
    const int SM1 = 2 * (1*ASZ + 1*BSZ) * 4;
    cudaFuncSetAttribute((const void*)g1_bf16,            cudaFuncAttributeMaxDynamicSharedMemorySize, G1_SMEM);
    cudaFuncSetAttribute((const void*)gemm_tc<1,3,false>, cudaFuncAttributeMaxDynamicSharedMemorySize, SM3);
    cudaFuncSetAttribute((const void*)gemm_tc<2,1,false>, cudaFuncAttributeMaxDynamicSharedMemorySize, SM1);
    cudaFuncSetAttribute((const void*)gemm_tc<3,1,true >, cudaFuncAttributeMaxDynamicSharedMemorySize, SM1);

    const dim3 blk(256);

    // G1: reduce 1x1 conv + BN + ReLU, bf16 triple-product. N = 64*196 exact.
    {
        const dim3 g(98, 4, 1);
        g1_bf16<<<g, blk, G1_SMEM>>>(reduce_w, feature2, sx,
                                     reduce_b, reduce_gamma, reduce_beta,
                                     reduce_mean, reduce_var);
        g1_bf16<<<g, blk, G1_SMEM>>>(reduce_w, feature3, sx + (size_t)64 * 512 * NB,
                                     reduce_b, reduce_gamma, reduce_beta,
                                     reduce_mean, reduce_var);
    }
    // G2: e = exp(-xf xf^T), symmetric lower-tri + mirror. M=N=512, K=196
    {
        const dim3 g(10, 1, 128);
        gemm_tc<1,3,false><<<g, blk, SM3>>>(sx, sx, se,
                               512, 512, 196, 196, 196, 512,
                               512LL * 196, 512LL * 196, 512LL * 512,
                               nullptr, nullptr, nullptr, nullptr, nullptr,
                               srs, 4);
    }
    // G3: y = (e @ xf) / rowsum. M=512, N=196, K=512 (per batch), 1-term paired-B
    {
        const dim3 g(2, 4, 128);
        gemm_tc<2,1,false><<<g, blk, SM1>>>(se, sx, sy,
                               512, 196, 512, 512, 196, 196,
                               512LL * 512, 512LL * 196, 512LL * 196,
                               nullptr, nullptr, nullptr, nullptr, nullptr,
                               srs, 4);
    }
    // G4: 3x3 conv (im2col) + BN + ReLU + pooled partials, 1-term paired-B, batched-N.
    {
        zero_kernel<<<192, 1024>>>(szp, 128*512*3);
        const dim3 g(196, 4, 1);
        gemm_tc<3,1,true><<<g, blk, SM1>>>(conv3_w, sy, nullptr,
                               512, 128*NB, 4608, 4608, 0, 0,
                               0LL, 512LL * NB, 0LL,
                               conv3_b, conv3_gamma, conv3_beta, conv3_mean, conv3_var,
                               szp, 3);
    }
    fc_kernel<<<128, 256>>>(szp, fc1_w, fc1_b, fc2_w, fc2_b, sfc);
    combine_kernel<<<50, 256>>>(sfc, out);
}